// round 13
// baseline (speedup 1.0000x reference)
#include <cuda_runtime.h>
#include <cuda_fp16.h>
#include <math.h>
#include <stdint.h>

#define BDIM   2
#define NSEQ   2048
#define CIN    256
#define COOR   3
#define HEADS  8
#define DHEAD  64
#define DINNER 512
#define EDIM   192
#define BN     (BDIM*NSEQ)     // 4096

// attention tiling (halves)
#define QSTRH  200
#define VSTRH  200
#define KVT    32
#define NKT    (NSEQ/KVT)

// projection tiling
#define AK2    72    // GEMM smem row stride (halves)
#define KC     64    // K-chunk

// Scratch (fp16)
__device__ __half g_q  [BDIM*HEADS*NSEQ*EDIM];
__device__ __half g_k  [BDIM*HEADS*NSEQ*EDIM];
__device__ __half g_v  [BDIM*HEADS*NSEQ*EDIM];
__device__ __half g_aoh[COOR*BN*DINNER];     // attn out planes [c][bn][h*64+d]
__device__ __half g_xh [COOR*BN*CIN];        // [c][bn][i]
__device__ __half g_wh [3*DINNER*CIN];       // [wsel][o][i]
__device__ __half g_woh[CIN*DINNER];         // [o][i]

__device__ __forceinline__ void mma_f16(float* c, const unsigned* a, const unsigned* b) {
    asm volatile(
        "mma.sync.aligned.m16n8k16.row.col.f32.f16.f16.f32 "
        "{%0,%1,%2,%3}, {%4,%5,%6,%7}, {%8,%9}, {%0,%1,%2,%3};"
        : "+f"(c[0]), "+f"(c[1]), "+f"(c[2]), "+f"(c[3])
        : "r"(a[0]), "r"(a[1]), "r"(a[2]), "r"(a[3]), "r"(b[0]), "r"(b[1]));
}
__device__ __forceinline__ void ldsm_x4(unsigned* r, uint32_t addr) {
    asm volatile("ldmatrix.sync.aligned.m8n8.x4.shared.b16 {%0,%1,%2,%3}, [%4];"
        : "=r"(r[0]), "=r"(r[1]), "=r"(r[2]), "=r"(r[3]) : "r"(addr));
}
__device__ __forceinline__ void ldsm_x4_t(unsigned* r, uint32_t addr) {
    asm volatile("ldmatrix.sync.aligned.m8n8.x4.trans.shared.b16 {%0,%1,%2,%3}, [%4];"
        : "=r"(r[0]), "=r"(r[1]), "=r"(r[2]), "=r"(r[3]) : "r"(addr));
}
__device__ __forceinline__ uint32_t smem_u32(const void* p) {
    uint32_t a;
    asm("{ .reg .u64 t; cvta.to.shared.u64 t, %1; cvt.u32.u64 %0, t; }"
        : "=r"(a) : "l"(p));
    return a;
}
__device__ __forceinline__ void cp16(uint32_t dst, const void* src) {
    asm volatile("cp.async.ca.shared.global [%0], [%1], 16;" :: "r"(dst), "l"(src));
}
__device__ __forceinline__ unsigned packh2(float a, float b) {
    __half2 h = __floats2half2_rn(a, b);
    return *(unsigned*)&h;
}
#define CP_COMMIT() asm volatile("cp.async.commit_group;" ::: "memory")
#define CP_WAITN(n) asm volatile("cp.async.wait_group %0;" :: "n"(n) : "memory")

// ===========================================================================
// Converts
// ===========================================================================
__global__ __launch_bounds__(256) void conv_x_kernel(const float* __restrict__ x)
{
    int idx = blockIdx.x * 256 + threadIdx.x;
#pragma unroll
    for (int c = 0; c < 3; c++)
        g_xh[c * (BN * CIN) + idx] = __float2half(x[(size_t)idx * 3 + c]);
}
__global__ __launch_bounds__(256) void conv_w_kernel(
    const float* __restrict__ Wq, const float* __restrict__ Wk,
    const float* __restrict__ Wv, const float* __restrict__ Wo)
{
    int idx = blockIdx.x * 256 + threadIdx.x;
    if (idx < 3 * DINNER * CIN) {
        int wsel = idx / (DINNER * CIN), rem = idx % (DINNER * CIN);
        const float* W = (wsel == 0) ? Wq : (wsel == 1 ? Wk : Wv);
        g_wh[idx] = __float2half(W[rem]);
    } else {
        int rem = idx - 3 * DINNER * CIN;
        g_woh[rem] = __float2half(Wo[rem]);
    }
}

// ===========================================================================
// GEMM smem layout (shared by qkv4/oproj4)
// ===========================================================================
#define GA_OFF(s)  ((s) * 128 * AK2)
#define GW_BASE    (3 * 128 * AK2)
#define GW_OFF(s)  (GW_BASE + (s) * 64 * AK2)
#define G_SMEMH    (GW_BASE + 3 * 64 * AK2)

// ===========================================================================
// Kernel 1: QKV GEMM. grid (BN/128, DINNER/64, 9), block 256.
// ===========================================================================
__global__ __launch_bounds__(256, 2) void qkv4_kernel()
{
    extern __shared__ __half smh[];
    uint32_t sb = smem_u32(smh);

    int z    = blockIdx.z;
    int wsel = z / 3, cc = z % 3;
    __half* outp = (wsel == 0) ? g_q : (wsel == 1 ? g_k : g_v);
    const __half* Ap = g_xh + (size_t)cc * (BN * CIN);
    const __half* Wp = g_wh + (size_t)wsel * (DINNER * CIN);

    int bn0 = blockIdx.x * 128;
    int o0  = blockIdx.y * 64;
    int tid = threadIdx.x;
    int warp = tid >> 5, lane = tid & 31;
    int gID = lane >> 2, tig = lane & 3;
    int m0  = warp * 16;

    int l7   = lane & 7;
    int lh8  = (lane >> 3) & 1;
    int lh16 = lane >> 4;
    uint32_t a_off = (uint32_t)((m0 + l7 + 8 * lh8) * AK2 + 8 * lh16) * 2;
    uint32_t b_off = (uint32_t)((l7 + 8 * lh16) * AK2 + 8 * lh8) * 2;

    float o_acc[8][4];
#pragma unroll
    for (int nt = 0; nt < 8; nt++)
#pragma unroll
        for (int i = 0; i < 4; i++) o_acc[nt][i] = 0.f;

    const int NC = CIN / KC;   // 4
    auto issue = [&](int stage, int kc) {
        int k0 = kc * KC;
#pragma unroll
        for (int j = 0; j < 4; j++) {
            int l = tid + j * 256, r = l >> 3, seg = l & 7;
            cp16(sb + (GA_OFF(stage) + r * AK2 + seg * 8) * 2,
                 Ap + (size_t)(bn0 + r) * CIN + k0 + seg * 8);
        }
#pragma unroll
        for (int j = 0; j < 2; j++) {
            int l = tid + j * 256, r = l >> 3, seg = l & 7;
            cp16(sb + (GW_OFF(stage) + r * AK2 + seg * 8) * 2,
                 Wp + (size_t)(o0 + r) * CIN + k0 + seg * 8);
        }
        CP_COMMIT();
    };

    issue(0, 0);
    issue(1, 1);

    for (int kc = 0; kc < NC; kc++) {
        if (kc + 2 < NC) { issue((kc + 2) % 3, kc + 2); CP_WAITN(2); }
        else if (kc + 1 < NC) CP_WAITN(1);
        else                  CP_WAITN(0);
        __syncthreads();

        uint32_t ab = sb + GA_OFF(kc % 3) * 2 + a_off;
        uint32_t wb = sb + GW_OFF(kc % 3) * 2 + b_off;
#pragma unroll
        for (int ks = 0; ks < KC / 16; ks++) {
            unsigned a[4];
            ldsm_x4(a, ab + (uint32_t)(16 * ks) * 2);
#pragma unroll
            for (int p = 0; p < 4; p++) {
                unsigned bb[4];
                ldsm_x4(bb, wb + (uint32_t)(16 * p * AK2 + 16 * ks) * 2);
                mma_f16(o_acc[2 * p],     a, bb);
                mma_f16(o_acc[2 * p + 1], a, bb + 2);
            }
        }
        __syncthreads();
    }

#pragma unroll
    for (int i = 0; i < 2; i++) {
        int bn = bn0 + m0 + gID + 8 * i;
        int b = bn >> 11, n = bn & (NSEQ - 1);
#pragma unroll
        for (int nt = 0; nt < 8; nt++) {
#pragma unroll
            for (int hh = 0; hh < 2; hh++) {
                int o = o0 + 8 * nt + 2 * tig + hh;
                int hd = o >> 6, d = o & 63;
                outp[((size_t)(b * HEADS + hd) * NSEQ + n) * EDIM + d * 3 + cc] =
                    __float2half(o_acc[nt][2 * i + hh]);
            }
        }
    }
}

// ===========================================================================
// Kernel 2: flash attention; register P + cross-tile software pipeline:
// iter t runs exp(t), then PV(t) interleaved with QK(t+1).
// grid (NSEQ/128, B*H), block 256.
// ===========================================================================
#define SMQ  0
#define SMK  (128*QSTRH)                   // 25600
#define SMV  (SMK + 2*KVT*QSTRH)           // 38400
#define SMTOT_H (SMV + 2*KVT*VSTRH)        // 51200 halves = 102400 B

__global__ __launch_bounds__(256, 1) void attn7_kernel()
{
    extern __shared__ __half smh[];
    __half* Qs = smh + SMQ;

    uint32_t q_u  = smem_u32(smh + SMQ);
    uint32_t k_u[2] = { smem_u32(smh + SMK), smem_u32(smh + SMK + KVT * QSTRH) };
    uint32_t v_u[2] = { smem_u32(smh + SMV), smem_u32(smh + SMV + KVT * VSTRH) };

    int tid  = threadIdx.x;
    int warp = tid >> 5, lane = tid & 31;
    int gID  = lane >> 2, tig = lane & 3;
    int bh   = blockIdx.y;
    int b    = bh >> 3, h = bh & 7;
    int row0 = blockIdx.x * 128;
    int m0   = warp * 16;

    const __half* qb = g_q + (size_t)bh * NSEQ * EDIM;
    const __half* kb = g_k + (size_t)bh * NSEQ * EDIM;
    const __half* vb = g_v + (size_t)bh * NSEQ * EDIM;

    int l7   = lane & 7;
    int lh8  = (lane >> 3) & 1;
    int lh16 = lane >> 4;
    uint32_t qa_off = (uint32_t)((m0 + l7 + 8 * lh8) * QSTRH + 8 * lh16) * 2;
    uint32_t kb_off = (uint32_t)((l7 + 8 * lh16) * QSTRH + 8 * lh8) * 2;
    uint32_t vb_off = (uint32_t)((l7 + 8 * lh8) * VSTRH + 8 * lh16) * 2;

    // load Q tile to smem
#pragma unroll
    for (int j = 0; j < 12; j++) {
        int l = tid + j * 256, r = l / 24, e8 = l % 24;
        *(uint4*)(Qs + r * QSTRH + e8 * 8) =
            *(const uint4*)(qb + (size_t)(row0 + r) * EDIM + e8 * 8);
    }

    // K/V tile load helpers (3 x 16B per thread each)
    auto load_k = [&](int buf, int t) {
        const __half* src = kb + (size_t)t * KVT * EDIM;
#pragma unroll
        for (int j = 0; j < 3; j++) {
            int l = tid + j * 256, r = l / 24, e8 = l % 24;
            cp16(k_u[buf] + (uint32_t)(r * QSTRH + e8 * 8) * 2, src + (size_t)r * EDIM + e8 * 8);
        }
    };
    auto load_v = [&](int buf, int t) {
        const __half* src = vb + (size_t)t * KVT * EDIM;
#pragma unroll
        for (int j = 0; j < 3; j++) {
            int l = tid + j * 256, r = l / 24, e8 = l % 24;
            cp16(v_u[buf] + (uint32_t)(r * VSTRH + e8 * 8) * 2, src + (size_t)r * EDIM + e8 * 8);
        }
    };

    // prologue loads: K0->k0, V0->v0, K1->k1
    load_k(0, 0);
    load_v(0, 0);
    load_k(1, 1);
    CP_COMMIT();
    __syncthreads();   // Q store visible

    // hoist Q a-frags into registers
    unsigned qf[12][4];
#pragma unroll
    for (int ks = 0; ks < 12; ks++)
        ldsm_x4(qf[ks], q_u + qa_off + (uint32_t)(16 * ks) * 2);

    float o_acc[24][4];
#pragma unroll
    for (int nt = 0; nt < 24; nt++)
#pragma unroll
        for (int i = 0; i < 4; i++) o_acc[nt][i] = 0.f;
    float lsum0 = 0.f, lsum1 = 0.f;

    const float scl2 = 0.07216878364870322f * 1.4426950408889634f;

    CP_WAITN(0);
    __syncthreads();

    // prologue compute: QK(0)
    float s[4][4];
#pragma unroll
    for (int nt = 0; nt < 4; nt++)
#pragma unroll
        for (int i = 0; i < 4; i++) s[nt][i] = 0.f;
#pragma unroll
    for (int ks = 0; ks < 12; ks++) {
#pragma unroll
        for (int p = 0; p < 2; p++) {
            unsigned bb[4];
            ldsm_x4(bb, k_u[0] + kb_off + (uint32_t)(16 * p * QSTRH + 16 * ks) * 2);
            mma_f16(s[2 * p],     qf[ks], bb);
            mma_f16(s[2 * p + 1], qf[ks], bb + 2);
        }
    }

    for (int t = 0; t < NKT; t++) {
        bool more1 = (t + 1 < NKT);   // QK(t+1) exists
        bool more2 = (t + 2 < NKT);   // K(t+2) needed
        int vcur = t & 1;
        int knxt = (t + 1) & 1;

        // ---- exp2(t) -> register P a-frags ----
        unsigned pf[2][4];
#pragma unroll
        for (int kt = 0; kt < 2; kt++) {
#pragma unroll
            for (int q = 0; q < 2; q++) {
                float p0 = exp2f(s[2 * kt + q][0] * scl2);
                float p1 = exp2f(s[2 * kt + q][1] * scl2);
                float p2 = exp2f(s[2 * kt + q][2] * scl2);
                float p3 = exp2f(s[2 * kt + q][3] * scl2);
                lsum0 += p0 + p1;
                lsum1 += p2 + p3;
                pf[kt][q]     = packh2(p0, p1);
                pf[kt][q + 2] = packh2(p2, p3);
            }
            unsigned tmp = pf[kt][1]; pf[kt][1] = pf[kt][2]; pf[kt][2] = tmp;
        }

        // ---- issue next loads: K(t+2) -> k_u[t&1], V(t+1) -> v_u[(t+1)&1] ----
        if (more2) load_k(t & 1, t + 2);
        if (more1) load_v(knxt, t + 1);
        CP_COMMIT();

        // ---- zero s for QK(t+1) ----
        if (more1) {
#pragma unroll
            for (int nt = 0; nt < 4; nt++)
#pragma unroll
                for (int i = 0; i < 4; i++) s[nt][i] = 0.f;
        }

        // ---- interleaved: PV(t) (24 units) + QK(t+1) (12 units) ----
#pragma unroll
        for (int ks = 0; ks < 12; ks++) {
            if (more1) {
#pragma unroll
                for (int p = 0; p < 2; p++) {
                    unsigned bb[4];
                    ldsm_x4(bb, k_u[knxt] + kb_off + (uint32_t)(16 * p * QSTRH + 16 * ks) * 2);
                    mma_f16(s[2 * p],     qf[ks], bb);
                    mma_f16(s[2 * p + 1], qf[ks], bb + 2);
                }
            }
#pragma unroll
            for (int u = 0; u < 2; u++) {
                int idx = 2 * ks + u;        // 0..23
                int kt = idx / 12, g = idx % 12;
                unsigned vv[4];
                ldsm_x4_t(vv, v_u[vcur] + vb_off + (uint32_t)(16 * kt * VSTRH + 16 * g) * 2);
                mma_f16(o_acc[2 * g],     pf[kt], vv);
                mma_f16(o_acc[2 * g + 1], pf[kt], vv + 2);
            }
        }

        CP_WAITN(0);
        __syncthreads();
    }

    lsum0 += __shfl_xor_sync(0xffffffffu, lsum0, 1);
    lsum0 += __shfl_xor_sync(0xffffffffu, lsum0, 2);
    lsum1 += __shfl_xor_sync(0xffffffffu, lsum1, 1);
    lsum1 += __shfl_xor_sync(0xffffffffu, lsum1, 2);
    float inv0 = 1.f / lsum0, inv1 = 1.f / lsum1;

    // epilogue -> fp16 planes g_aoh[c][bn][h*64+d]
    int n0 = row0 + m0 + gID;
    int n1 = n0 + 8;
    size_t bn0i = (size_t)(b * NSEQ + n0) * DINNER + h * DHEAD;
    size_t bn1i = (size_t)(b * NSEQ + n1) * DINNER + h * DHEAD;
#pragma unroll
    for (int nt = 0; nt < 24; nt++) {
#pragma unroll
        for (int hh = 0; hh < 2; hh++) {
            int e = 8 * nt + 2 * tig + hh;
            int d = e / 3, c = e - 3 * d;
            g_aoh[(size_t)c * (BN * DINNER) + bn0i + d] = __float2half(o_acc[nt][hh]     * inv0);
            g_aoh[(size_t)c * (BN * DINNER) + bn1i + d] = __float2half(o_acc[nt][2 + hh] * inv1);
        }
    }
}

// ===========================================================================
// Kernel 3: output projection GEMM. grid (BN/128, CIN/64, 3), block 256.
// ===========================================================================
__global__ __launch_bounds__(256, 2) void oproj4_kernel(float* __restrict__ out)
{
    extern __shared__ __half smh[];
    uint32_t sb = smem_u32(smh);

    int cc  = blockIdx.z;
    const __half* Ap = g_aoh + (size_t)cc * (BN * DINNER);
    const __half* Wp = g_woh;

    int bn0 = blockIdx.x * 128;
    int o0  = blockIdx.y * 64;
    int tid = threadIdx.x;
    int warp = tid >> 5, lane = tid & 31;
    int gID = lane >> 2, tig = lane & 3;
    int m0  = warp * 16;

    int l7   = lane & 7;
    int lh8  = (lane >> 3) & 1;
    int lh16 = lane >> 4;
    uint32_t a_off = (uint32_t)((m0 + l7 + 8 * lh8) * AK2 + 8 * lh16) * 2;
    uint32_t b_off = (uint32_t)((l7 + 8 * lh16) * AK2 + 8 * lh8) * 2;

    float o_acc[8][4];
#pragma unroll
    for (int nt = 0; nt < 8; nt++)
#pragma unroll
        for (int i = 0; i < 4; i++) o_acc[nt][i] = 0.f;

    const int NC = DINNER / KC;   // 8
    auto issue = [&](int stage, int kc) {
        int k0 = kc * KC;
#pragma unroll
        for (int j = 0; j < 4; j++) {
            int l = tid + j * 256, r = l >> 3, seg = l & 7;
            cp16(sb + (GA_OFF(stage) + r * AK2 + seg * 8) * 2,
                 Ap + (size_t)(bn0 + r) * DINNER + k0 + seg * 8);
        }
#pragma unroll
        for (int j = 0; j < 2; j++) {
            int l = tid + j * 256, r = l >> 3, seg = l & 7;
            cp16(sb + (GW_OFF(stage) + r * AK2 + seg * 8) * 2,
                 Wp + (size_t)(o0 + r) * DINNER + k0 + seg * 8);
        }
        CP_COMMIT();
    };

    issue(0, 0);
    issue(1, 1);

    for (int kc = 0; kc < NC; kc++) {
        if (kc + 2 < NC) { issue((kc + 2) % 3, kc + 2); CP_WAITN(2); }
        else if (kc + 1 < NC) CP_WAITN(1);
        else                  CP_WAITN(0);
        __syncthreads();

        uint32_t ab = sb + GA_OFF(kc % 3) * 2 + a_off;
        uint32_t wb = sb + GW_OFF(kc % 3) * 2 + b_off;
#pragma unroll
        for (int ks = 0; ks < KC / 16; ks++) {
            unsigned a[4];
            ldsm_x4(a, ab + (uint32_t)(16 * ks) * 2);
#pragma unroll
            for (int p = 0; p < 4; p++) {
                unsigned bb[4];
                ldsm_x4(bb, wb + (uint32_t)(16 * p * AK2 + 16 * ks) * 2);
                mma_f16(o_acc[2 * p],     a, bb);
                mma_f16(o_acc[2 * p + 1], a, bb + 2);
            }
        }
        __syncthreads();
    }

#pragma unroll
    for (int i = 0; i < 2; i++) {
        int bn = bn0 + m0 + gID + 8 * i;
#pragma unroll
        for (int nt = 0; nt < 8; nt++) {
#pragma unroll
            for (int hh = 0; hh < 2; hh++) {
                int o = o0 + 8 * nt + 2 * tig + hh;
                out[((size_t)bn * CIN + o) * 3 + cc] = o_acc[nt][2 * i + hh];
            }
        }
    }
}

// ---------------------------------------------------------------------------
extern "C" void kernel_launch(void* const* d_in, const int* in_sizes, int n_in,
                              void* d_out, int out_size)
{
    const float* x  = (const float*)d_in[0];
    const float* Wq = (const float*)d_in[1];
    const float* Wk = (const float*)d_in[2];
    const float* Wv = (const float*)d_in[3];
    const float* Wo = (const float*)d_in[4];
    float* out = (float*)d_out;

    const int g_smem    = G_SMEMH * 2;     // 82944 B
    const int attn_smem = SMTOT_H * 2;     // 102400 B

    cudaFuncSetAttribute(qkv4_kernel,
                         cudaFuncAttributeMaxDynamicSharedMemorySize, g_smem);
    cudaFuncSetAttribute(attn7_kernel,
                         cudaFuncAttributeMaxDynamicSharedMemorySize, attn_smem);
    cudaFuncSetAttribute(oproj4_kernel,
                         cudaFuncAttributeMaxDynamicSharedMemorySize, g_smem);

    conv_x_kernel<<<BN * CIN / 256, 256>>>(x);
    conv_w_kernel<<<(3 * DINNER * CIN + CIN * DINNER) / 256, 256>>>(Wq, Wk, Wv, Wo);
    qkv4_kernel<<<dim3(BN / 128, DINNER / 64, 9), 256, g_smem>>>();
    attn7_kernel<<<dim3(NSEQ / 128, BDIM * HEADS), 256, attn_smem>>>();
    oproj4_kernel<<<dim3(BN / 128, CIN / 64, 3), 256, g_smem>>>(out);
}

// round 14
// speedup vs baseline: 1.1986x; 1.1986x over previous
#include <cuda_runtime.h>
#include <cuda_fp16.h>
#include <math.h>
#include <stdint.h>

#define BDIM   2
#define NSEQ   2048
#define CIN    256
#define COOR   3
#define HEADS  8
#define DHEAD  64
#define DINNER 512
#define EDIM   192
#define BN     (BDIM*NSEQ)     // 4096

// attention tiling (halves)
#define QSTRH  200
#define VSTRH  200
#define KVT    32
#define NKT    (NSEQ/KVT)

// projection tiling
#define AK2    72    // GEMM smem row stride (halves)
#define KC     64    // K-chunk

// Scratch (fp16)
__device__ __half g_q  [BDIM*HEADS*NSEQ*EDIM];
__device__ __half g_k  [BDIM*HEADS*NSEQ*EDIM];
__device__ __half g_v  [BDIM*HEADS*NSEQ*EDIM];
__device__ __half g_aoh[COOR*BN*DINNER];     // attn out planes [c][bn][h*64+d]
__device__ __half g_xh [COOR*BN*CIN];        // [c][bn][i]
__device__ __half g_wh [3*DINNER*CIN];       // [wsel][o][i]
__device__ __half g_woh[CIN*DINNER];         // [o][i]

__device__ __forceinline__ void mma_f16(float* c, const unsigned* a, const unsigned* b) {
    asm volatile(
        "mma.sync.aligned.m16n8k16.row.col.f32.f16.f16.f32 "
        "{%0,%1,%2,%3}, {%4,%5,%6,%7}, {%8,%9}, {%0,%1,%2,%3};"
        : "+f"(c[0]), "+f"(c[1]), "+f"(c[2]), "+f"(c[3])
        : "r"(a[0]), "r"(a[1]), "r"(a[2]), "r"(a[3]), "r"(b[0]), "r"(b[1]));
}
__device__ __forceinline__ void ldsm_x4(unsigned* r, uint32_t addr) {
    asm volatile("ldmatrix.sync.aligned.m8n8.x4.shared.b16 {%0,%1,%2,%3}, [%4];"
        : "=r"(r[0]), "=r"(r[1]), "=r"(r[2]), "=r"(r[3]) : "r"(addr));
}
__device__ __forceinline__ void ldsm_x4_t(unsigned* r, uint32_t addr) {
    asm volatile("ldmatrix.sync.aligned.m8n8.x4.trans.shared.b16 {%0,%1,%2,%3}, [%4];"
        : "=r"(r[0]), "=r"(r[1]), "=r"(r[2]), "=r"(r[3]) : "r"(addr));
}
__device__ __forceinline__ uint32_t smem_u32(const void* p) {
    uint32_t a;
    asm("{ .reg .u64 t; cvta.to.shared.u64 t, %1; cvt.u32.u64 %0, t; }"
        : "=r"(a) : "l"(p));
    return a;
}
__device__ __forceinline__ void cp16(uint32_t dst, const void* src) {
    asm volatile("cp.async.ca.shared.global [%0], [%1], 16;" :: "r"(dst), "l"(src));
}
__device__ __forceinline__ unsigned packh2(float a, float b) {
    __half2 h = __floats2half2_rn(a, b);
    return *(unsigned*)&h;
}
#define CP_COMMIT() asm volatile("cp.async.commit_group;" ::: "memory")
#define CP_WAITN(n) asm volatile("cp.async.wait_group %0;" :: "n"(n) : "memory")

// ===========================================================================
// Converts
// ===========================================================================
__global__ __launch_bounds__(256) void conv_x_kernel(const float* __restrict__ x)
{
    int idx = blockIdx.x * 256 + threadIdx.x;
#pragma unroll
    for (int c = 0; c < 3; c++)
        g_xh[c * (BN * CIN) + idx] = __float2half(x[(size_t)idx * 3 + c]);
}
__global__ __launch_bounds__(256) void conv_w_kernel(
    const float* __restrict__ Wq, const float* __restrict__ Wk,
    const float* __restrict__ Wv, const float* __restrict__ Wo)
{
    int idx = blockIdx.x * 256 + threadIdx.x;
    if (idx < 3 * DINNER * CIN) {
        int wsel = idx / (DINNER * CIN), rem = idx % (DINNER * CIN);
        const float* W = (wsel == 0) ? Wq : (wsel == 1 ? Wk : Wv);
        g_wh[idx] = __float2half(W[rem]);
    } else {
        int rem = idx - 3 * DINNER * CIN;
        g_woh[rem] = __float2half(Wo[rem]);
    }
}

// ===========================================================================
// Kernel 1: QKV GEMM, M=128 N=128, 2-stage cp.async.
// grid (BN/128, DINNER/128, 9), block 256 (8 warps, each 16 rows x 128 cols).
// ===========================================================================
#define Q5_A(s)   ((s) * 128 * AK2)
#define Q5_WB     (2 * 128 * AK2)
#define Q5_W(s)   (Q5_WB + (s) * 128 * AK2)
#define Q5_SMEMH  (Q5_WB + 2 * 128 * AK2)    // 36864 halves = 73728 B

__global__ __launch_bounds__(256, 2) void qkv5_kernel()
{
    extern __shared__ __half smh[];
    uint32_t sb = smem_u32(smh);

    int z    = blockIdx.z;
    int wsel = z / 3, cc = z % 3;
    __half* outp = (wsel == 0) ? g_q : (wsel == 1 ? g_k : g_v);
    const __half* Ap = g_xh + (size_t)cc * (BN * CIN);
    const __half* Wp = g_wh + (size_t)wsel * (DINNER * CIN);

    int bn0 = blockIdx.x * 128;
    int o0  = blockIdx.y * 128;
    int tid = threadIdx.x;
    int warp = tid >> 5, lane = tid & 31;
    int gID = lane >> 2, tig = lane & 3;
    int m0  = warp * 16;

    int l7   = lane & 7;
    int lh8  = (lane >> 3) & 1;
    int lh16 = lane >> 4;
    uint32_t a_off = (uint32_t)((m0 + l7 + 8 * lh8) * AK2 + 8 * lh16) * 2;
    uint32_t b_off = (uint32_t)((l7 + 8 * lh16) * AK2 + 8 * lh8) * 2;

    float o_acc[16][4];
#pragma unroll
    for (int nt = 0; nt < 16; nt++)
#pragma unroll
        for (int i = 0; i < 4; i++) o_acc[nt][i] = 0.f;

    const int NC = CIN / KC;   // 4
    auto issue = [&](int stage, int kc) {
        int k0 = kc * KC;
#pragma unroll
        for (int j = 0; j < 4; j++) {
            int l = tid + j * 256, r = l >> 3, seg = l & 7;
            cp16(sb + (Q5_A(stage) + r * AK2 + seg * 8) * 2,
                 Ap + (size_t)(bn0 + r) * CIN + k0 + seg * 8);
        }
#pragma unroll
        for (int j = 0; j < 4; j++) {
            int l = tid + j * 256, r = l >> 3, seg = l & 7;
            cp16(sb + (Q5_W(stage) + r * AK2 + seg * 8) * 2,
                 Wp + (size_t)(o0 + r) * CIN + k0 + seg * 8);
        }
        CP_COMMIT();
    };

    issue(0, 0);

    for (int kc = 0; kc < NC; kc++) {
        bool more = (kc + 1 < NC);
        if (more) { issue((kc + 1) & 1, kc + 1); CP_WAITN(1); }
        else      CP_WAITN(0);
        __syncthreads();

        uint32_t ab = sb + Q5_A(kc & 1) * 2 + a_off;
        uint32_t wb = sb + Q5_W(kc & 1) * 2 + b_off;
#pragma unroll
        for (int ks = 0; ks < KC / 16; ks++) {
            unsigned a[4];
            ldsm_x4(a, ab + (uint32_t)(16 * ks) * 2);
#pragma unroll
            for (int p = 0; p < 8; p++) {
                unsigned bb[4];
                ldsm_x4(bb, wb + (uint32_t)(16 * p * AK2 + 16 * ks) * 2);
                mma_f16(o_acc[2 * p],     a, bb);
                mma_f16(o_acc[2 * p + 1], a, bb + 2);
            }
        }
        __syncthreads();
    }

#pragma unroll
    for (int i = 0; i < 2; i++) {
        int bn = bn0 + m0 + gID + 8 * i;
        int b = bn >> 11, n = bn & (NSEQ - 1);
#pragma unroll
        for (int nt = 0; nt < 16; nt++) {
#pragma unroll
            for (int hh = 0; hh < 2; hh++) {
                int o = o0 + 8 * nt + 2 * tig + hh;
                int hd = o >> 6, d = o & 63;
                outp[((size_t)(b * HEADS + hd) * NSEQ + n) * EDIM + d * 3 + cc] =
                    __float2half(o_acc[nt][2 * i + hh]);
            }
        }
    }
}

// ===========================================================================
// Kernel 2: flash attention (attn6 core) + smem-staged coalesced epilogue.
// grid (NSEQ/128, B*H), block 256.
// ===========================================================================
#define SMQ  0
#define SMK  (128*QSTRH)                   // 25600
#define SMV  (SMK + 2*KVT*QSTRH)           // 38400
#define SMTOT_H (SMV + 2*KVT*VSTRH)        // 51200 halves = 102400 B

__global__ __launch_bounds__(256, 1) void attn8_kernel()
{
    extern __shared__ __half smh[];
    __half* Qs = smh + SMQ;

    uint32_t q_u  = smem_u32(smh + SMQ);
    uint32_t k_u[2] = { smem_u32(smh + SMK), smem_u32(smh + SMK + KVT * QSTRH) };
    uint32_t v_u[2] = { smem_u32(smh + SMV), smem_u32(smh + SMV + KVT * VSTRH) };

    int tid  = threadIdx.x;
    int warp = tid >> 5, lane = tid & 31;
    int gID  = lane >> 2, tig = lane & 3;
    int bh   = blockIdx.y;
    int b    = bh >> 3, h = bh & 7;
    int row0 = blockIdx.x * 128;
    int m0   = warp * 16;

    const __half* qb = g_q + (size_t)bh * NSEQ * EDIM;
    const __half* kb = g_k + (size_t)bh * NSEQ * EDIM;
    const __half* vb = g_v + (size_t)bh * NSEQ * EDIM;

    int l7   = lane & 7;
    int lh8  = (lane >> 3) & 1;
    int lh16 = lane >> 4;
    uint32_t qa_off = (uint32_t)((m0 + l7 + 8 * lh8) * QSTRH + 8 * lh16) * 2;
    uint32_t kb_off = (uint32_t)((l7 + 8 * lh16) * QSTRH + 8 * lh8) * 2;
    uint32_t vb_off = (uint32_t)((l7 + 8 * lh8) * VSTRH + 8 * lh16) * 2;

    // load Q tile to smem
#pragma unroll
    for (int j = 0; j < 12; j++) {
        int l = tid + j * 256, r = l / 24, e8 = l % 24;
        *(uint4*)(Qs + r * QSTRH + e8 * 8) =
            *(const uint4*)(qb + (size_t)(row0 + r) * EDIM + e8 * 8);
    }

    // prologue: tile 0 K+V cp.async
#pragma unroll
    for (int j = 0; j < 3; j++) {
        int l = tid + j * 256, r = l / 24, e8 = l % 24;
        cp16(k_u[0] + (uint32_t)(r * QSTRH + e8 * 8) * 2, kb + (size_t)r * EDIM + e8 * 8);
        cp16(v_u[0] + (uint32_t)(r * VSTRH + e8 * 8) * 2, vb + (size_t)r * EDIM + e8 * 8);
    }
    CP_COMMIT();
    __syncthreads();

    // hoist Q a-frags into registers (loop-invariant)
    unsigned qf[12][4];
#pragma unroll
    for (int ks = 0; ks < 12; ks++)
        ldsm_x4(qf[ks], q_u + qa_off + (uint32_t)(16 * ks) * 2);

    float o_acc[24][4];
#pragma unroll
    for (int nt = 0; nt < 24; nt++)
#pragma unroll
        for (int i = 0; i < 4; i++) o_acc[nt][i] = 0.f;
    float lsum0 = 0.f, lsum1 = 0.f;

    const float scl2 = 0.07216878364870322f * 1.4426950408889634f;

    CP_WAITN(0);
    __syncthreads();

    for (int t = 0; t < NKT; t++) {
        int cur = t & 1, nb = cur ^ 1;
        bool more = (t + 1 < NKT);

        if (more) {
            const __half* kbt = kb + (size_t)(t + 1) * KVT * EDIM;
            const __half* vbt = vb + (size_t)(t + 1) * KVT * EDIM;
#pragma unroll
            for (int j = 0; j < 3; j++) {
                int l = tid + j * 256, r = l / 24, e8 = l % 24;
                cp16(k_u[nb] + (uint32_t)(r * QSTRH + e8 * 8) * 2, kbt + (size_t)r * EDIM + e8 * 8);
                cp16(v_u[nb] + (uint32_t)(r * VSTRH + e8 * 8) * 2, vbt + (size_t)r * EDIM + e8 * 8);
            }
            CP_COMMIT();
        }

        // ---- S = Q K^T ----
        float s[4][4];
#pragma unroll
        for (int nt = 0; nt < 4; nt++)
#pragma unroll
            for (int i = 0; i < 4; i++) s[nt][i] = 0.f;

#pragma unroll
        for (int ks = 0; ks < 12; ks++) {
#pragma unroll
            for (int p = 0; p < 2; p++) {
                unsigned bb[4];
                ldsm_x4(bb, k_u[cur] + kb_off + (uint32_t)(16 * p * QSTRH + 16 * ks) * 2);
                mma_f16(s[2 * p],     qf[ks], bb);
                mma_f16(s[2 * p + 1], qf[ks], bb + 2);
            }
        }

        // ---- exp2 -> register P a-frags ----
        unsigned pf[2][4];
#pragma unroll
        for (int kt = 0; kt < 2; kt++) {
#pragma unroll
            for (int q = 0; q < 2; q++) {
                float p0 = exp2f(s[2 * kt + q][0] * scl2);
                float p1 = exp2f(s[2 * kt + q][1] * scl2);
                float p2 = exp2f(s[2 * kt + q][2] * scl2);
                float p3 = exp2f(s[2 * kt + q][3] * scl2);
                lsum0 += p0 + p1;
                lsum1 += p2 + p3;
                pf[kt][q]     = packh2(p0, p1);
                pf[kt][q + 2] = packh2(p2, p3);
            }
            unsigned tmp = pf[kt][1]; pf[kt][1] = pf[kt][2]; pf[kt][2] = tmp;
        }

        // ---- O += P V ----
#pragma unroll
        for (int kt = 0; kt < 2; kt++) {
#pragma unroll
            for (int g = 0; g < 12; g++) {
                unsigned vv[4];
                ldsm_x4_t(vv, v_u[cur] + vb_off + (uint32_t)(16 * kt * VSTRH + 16 * g) * 2);
                mma_f16(o_acc[2 * g],     pf[kt], vv);
                mma_f16(o_acc[2 * g + 1], pf[kt], vv + 2);
            }
        }

        if (more) CP_WAITN(0);
        __syncthreads();
    }

    lsum0 += __shfl_xor_sync(0xffffffffu, lsum0, 1);
    lsum0 += __shfl_xor_sync(0xffffffffu, lsum0, 2);
    lsum1 += __shfl_xor_sync(0xffffffffu, lsum1, 1);
    lsum1 += __shfl_xor_sync(0xffffffffu, lsum1, 2);
    float inv0 = 1.f / lsum0, inv1 = 1.f / lsum1;

    // ---- epilogue: stage [row][e] in smem (reuse Qs), then coalesced planes ----
    {
        __half* Os = Qs;   // 128 x 200 region, free after qf hoist
        int r0 = m0 + gID, r1 = r0 + 8;
#pragma unroll
        for (int nt = 0; nt < 24; nt++) {
            int e = 8 * nt + 2 * tig;
            *(__half2*)(Os + r0 * QSTRH + e) =
                __floats2half2_rn(o_acc[nt][0] * inv0, o_acc[nt][1] * inv0);
            *(__half2*)(Os + r1 * QSTRH + e) =
                __floats2half2_rn(o_acc[nt][2] * inv1, o_acc[nt][3] * inv1);
        }
        __syncthreads();

        // 3 planes x 128 rows x 16 uint2 (4 d each) = 6144 items / 256 thr = 24
#pragma unroll
        for (int j = 0; j < 24; j++) {
            int i = tid + j * 256;
            int c = i >> 11;                  // /(128*16)
            int rem = i & 2047;
            int row = rem >> 4, d4 = rem & 15;
            __half vals[4];
#pragma unroll
            for (int q = 0; q < 4; q++)
                vals[q] = Os[row * QSTRH + 3 * (4 * d4 + q) + c];
            *(uint2*)(g_aoh + (size_t)c * (BN * DINNER)
                      + (size_t)(b * NSEQ + row0 + row) * DINNER + h * DHEAD + 4 * d4)
                = *(uint2*)vals;
        }
    }
}

// ===========================================================================
// Kernel 3: output projection GEMM, M=64.  grid (BN/64, CIN/64, 3), block 256.
// warp = (m-tile 0..3, n-half 0..1): 16 rows x 32 cols.
// ===========================================================================
#define O5_A(s)   ((s) * 64 * AK2)
#define O5_WB     (2 * 64 * AK2)
#define O5_W(s)   (O5_WB + (s) * 64 * AK2)
#define O5_SMEMH  (O5_WB + 2 * 64 * AK2)     // 18432 halves = 36864 B

__global__ __launch_bounds__(256, 4) void oproj5_kernel(float* __restrict__ out)
{
    extern __shared__ __half smh[];
    uint32_t sb = smem_u32(smh);

    int cc  = blockIdx.z;
    const __half* Ap = g_aoh + (size_t)cc * (BN * DINNER);
    const __half* Wp = g_woh;

    int bn0 = blockIdx.x * 64;
    int o0  = blockIdx.y * 64;
    int tid = threadIdx.x;
    int warp = tid >> 5, lane = tid & 31;
    int gID = lane >> 2, tig = lane & 3;
    int mt  = warp >> 1, nh = warp & 1;
    int m0  = mt * 16;

    int l7   = lane & 7;
    int lh8  = (lane >> 3) & 1;
    int lh16 = lane >> 4;
    uint32_t a_off = (uint32_t)((m0 + l7 + 8 * lh8) * AK2 + 8 * lh16) * 2;
    uint32_t b_off = (uint32_t)((nh * 32 + l7 + 8 * lh16) * AK2 + 8 * lh8) * 2;

    float o_acc[4][4];
#pragma unroll
    for (int nt = 0; nt < 4; nt++)
#pragma unroll
        for (int i = 0; i < 4; i++) o_acc[nt][i] = 0.f;

    const int NC = DINNER / KC;   // 8
    auto issue = [&](int stage, int kc) {
        int k0 = kc * KC;
#pragma unroll
        for (int j = 0; j < 2; j++) {
            int l = tid + j * 256, r = l >> 3, seg = l & 7;
            cp16(sb + (O5_A(stage) + r * AK2 + seg * 8) * 2,
                 Ap + (size_t)(bn0 + r) * DINNER + k0 + seg * 8);
        }
#pragma unroll
        for (int j = 0; j < 2; j++) {
            int l = tid + j * 256, r = l >> 3, seg = l & 7;
            cp16(sb + (O5_W(stage) + r * AK2 + seg * 8) * 2,
                 Wp + (size_t)(o0 + r) * DINNER + k0 + seg * 8);
        }
        CP_COMMIT();
    };

    issue(0, 0);

    for (int kc = 0; kc < NC; kc++) {
        bool more = (kc + 1 < NC);
        if (more) { issue((kc + 1) & 1, kc + 1); CP_WAITN(1); }
        else      CP_WAITN(0);
        __syncthreads();

        uint32_t ab = sb + O5_A(kc & 1) * 2 + a_off;
        uint32_t wb = sb + O5_W(kc & 1) * 2 + b_off;
#pragma unroll
        for (int ks = 0; ks < KC / 16; ks++) {
            unsigned a[4];
            ldsm_x4(a, ab + (uint32_t)(16 * ks) * 2);
#pragma unroll
            for (int p = 0; p < 2; p++) {
                unsigned bb[4];
                ldsm_x4(bb, wb + (uint32_t)(16 * p * AK2 + 16 * ks) * 2);
                mma_f16(o_acc[2 * p],     a, bb);
                mma_f16(o_acc[2 * p + 1], a, bb + 2);
            }
        }
        __syncthreads();
    }

#pragma unroll
    for (int i = 0; i < 2; i++) {
        int bn = bn0 + m0 + gID + 8 * i;
#pragma unroll
        for (int nt = 0; nt < 4; nt++) {
#pragma unroll
            for (int hh = 0; hh < 2; hh++) {
                int o = o0 + nh * 32 + 8 * nt + 2 * tig + hh;
                out[((size_t)bn * CIN + o) * 3 + cc] = o_acc[nt][2 * i + hh];
            }
        }
    }
}

// ---------------------------------------------------------------------------
extern "C" void kernel_launch(void* const* d_in, const int* in_sizes, int n_in,
                              void* d_out, int out_size)
{
    const float* x  = (const float*)d_in[0];
    const float* Wq = (const float*)d_in[1];
    const float* Wk = (const float*)d_in[2];
    const float* Wv = (const float*)d_in[3];
    const float* Wo = (const float*)d_in[4];
    float* out = (float*)d_out;

    const int q5_smem   = Q5_SMEMH * 2;    // 73728 B
    const int attn_smem = SMTOT_H * 2;     // 102400 B
    const int o5_smem   = O5_SMEMH * 2;    // 36864 B

    cudaFuncSetAttribute(qkv5_kernel,
                         cudaFuncAttributeMaxDynamicSharedMemorySize, q5_smem);
    cudaFuncSetAttribute(attn8_kernel,
                         cudaFuncAttributeMaxDynamicSharedMemorySize, attn_smem);
    cudaFuncSetAttribute(oproj5_kernel,
                         cudaFuncAttributeMaxDynamicSharedMemorySize, o5_smem);

    conv_x_kernel<<<BN * CIN / 256, 256>>>(x);
    conv_w_kernel<<<(3 * DINNER * CIN + CIN * DINNER) / 256, 256>>>(Wq, Wk, Wv, Wo);
    qkv5_kernel<<<dim3(BN / 128, DINNER / 128, 9), 256, q5_smem>>>();
    attn8_kernel<<<dim3(NSEQ / 128, BDIM * HEADS), 256, attn_smem>>>();
    oproj5_kernel<<<dim3(BN / 64, CIN / 64, 3), 256, o5_smem>>>(out);
}